// round 1
// baseline (speedup 1.0000x reference)
#include <cuda_runtime.h>
#include <cuda_bf16.h>
#include <math.h>

#define NCAM 6
#define CIN_IMG 512
#define MID 256
#define DBINS 112
#define HH 32
#define WW 88
#define NPIX (HH*WW)          // 2816
#define NVOX (128*128*16)     // 262144

// ---------------- device scratch (no allocations allowed) ----------------
__device__ float g_x [NCAM*MID*NPIX];     // 17.3 MB
__device__ float g_y [NCAM*MID*NPIX];     // 17.3 MB
__device__ float g_dp[NCAM*DBINS*NPIX];   //  7.6 MB
__device__ float g_gate[NCAM*MID];

// ---------------- gate / SE path (tiny) ----------------
__global__ void gate_kernel(const float* __restrict__ intr,
                            const float* __restrict__ w1, const float* __restrict__ b1,
                            const float* __restrict__ w2, const float* __restrict__ b2,
                            const float* __restrict__ rw, const float* __restrict__ rb,
                            const float* __restrict__ ew, const float* __restrict__ eb,
                            float* __restrict__ gate)
{
    int cam = blockIdx.x;
    int tid = threadIdx.x;   // 256
    __shared__ float sp_s;
    __shared__ float h[256], h2[256], t[256];

    if (tid == 0) {
        // 4x4 inverse via Gauss-Jordan (doubles), need inv[0][0], inv[1][1]
        double A[4][8];
        for (int r = 0; r < 4; r++) {
            for (int c = 0; c < 4; c++) A[r][c] = (double)intr[cam*16 + r*4 + c];
            for (int c = 0; c < 4; c++) A[r][4+c] = (r == c) ? 1.0 : 0.0;
        }
        for (int col = 0; col < 4; col++) {
            int piv = col; double best = fabs(A[col][col]);
            for (int r = col+1; r < 4; r++)
                if (fabs(A[r][col]) > best) { best = fabs(A[r][col]); piv = r; }
            if (piv != col)
                for (int c = 0; c < 8; c++) { double tmp = A[col][c]; A[col][c] = A[piv][c]; A[piv][c] = tmp; }
            double d = A[col][col];
            for (int c = 0; c < 8; c++) A[col][c] /= d;
            for (int r = 0; r < 4; r++) if (r != col) {
                double f = A[r][col];
                for (int c = 0; c < 8; c++) A[r][c] -= f * A[col][c];
            }
        }
        double i00 = A[0][4], i11 = A[1][5];
        sp_s = (float)(1000.0 * sqrt(i00*i00 + i11*i11));
    }
    __syncthreads();
    float sp = sp_s;

    h[tid] = fmaxf(sp * w1[tid] + b1[tid], 0.f);
    __syncthreads();

    float s = b2[tid];
    for (int k = 0; k < 256; k++) s += h[k] * w2[k*256 + tid];
    h2[tid] = s;
    __syncthreads();

    s = rb[tid];
    for (int c = 0; c < 256; c++) s += rw[tid*256 + c] * h2[c];
    t[tid] = fmaxf(s, 0.f);
    __syncthreads();

    s = eb[tid];
    for (int c = 0; c < 256; c++) s += ew[tid*256 + c] * t[c];
    gate[cam*256 + tid] = 1.f / (1.f + __expf(-s));
}

// ---------------- 3x3 conv, direct, smem-tiled ----------------
// MODE 0: out = relu(conv*s+b) * gate[cam][oc]
// MODE 1: out = relu(conv*s+b)
// MODE 2: out = relu(res + conv*s+b)        (res == out buffer is OK, per-element)
template<int CIN, int MODE>
__global__ __launch_bounds__(64)
void conv3x3_kernel(const float* __restrict__ in,          // [6][CIN][32][88]
                    const float* __restrict__ wgt,         // [256][CIN][3][3]
                    const float* __restrict__ scale,       // [256]
                    const float* __restrict__ bias,        // [256]
                    const float* __restrict__ gate_or_res,
                    float* __restrict__ out)               // [6][256][32][88]
{
    const int ct  = blockIdx.x;         // col tile: cols ct*32..+31 (last partial)
    const int rt  = blockIdx.y;         // row tile: rows rt*8..+7
    const int cam = blockIdx.z >> 5;
    const int kog = blockIdx.z & 31;    // out channels kog*8..+7
    const int tid = threadIdx.x;        // 64
    const int ty  = tid >> 3;           // 0..7
    const int tx  = tid & 7;            // 0..7 -> cols tx*4..tx*4+3
    const int tx4 = tx * 4;

    __shared__ float s_in[8][10][35];   // [ci][r][c], padded to 35 (conflict-free)
    __shared__ float s_w [8][8][9];     // [ko][ci][tap]

    const int row0 = rt * 8;
    const int col0 = ct * 32;

    float acc[4][8];
    #pragma unroll
    for (int p = 0; p < 4; p++)
        #pragma unroll
        for (int k = 0; k < 8; k++) acc[p][k] = 0.f;

    const float* inc = in  + (size_t)cam * CIN * NPIX;
    const float* wc  = wgt + (size_t)(kog*8) * CIN * 9;

    for (int ci0 = 0; ci0 < CIN; ci0 += 8) {
        // cooperative input tile load (8 ci x 10 r x 34 c), zero-padded halo
        for (int idx = tid; idx < 8*10*34; idx += 64) {
            int ci = idx / 340; int rem = idx % 340;
            int r = rem / 34;   int c   = rem % 34;
            int gh = row0 - 1 + r;
            int gw = col0 - 1 + c;
            float v = 0.f;
            if (gh >= 0 && gh < HH && gw >= 0 && gw < WW)
                v = inc[(size_t)(ci0 + ci) * NPIX + gh*WW + gw];
            s_in[ci][r][c] = v;
        }
        // weights: 8 ko x 8 ci x 9
        for (int idx = tid; idx < 576; idx += 64) {
            int ko = idx / 72; int rem = idx % 72;
            int ci = rem / 9;  int tap = rem % 9;
            s_w[ko][ci][tap] = wc[(size_t)ko * CIN * 9 + (size_t)(ci0 + ci) * 9 + tap];
        }
        __syncthreads();

        #pragma unroll 2
        for (int ci = 0; ci < 8; ci++) {
            float rin[3][6];
            #pragma unroll
            for (int r = 0; r < 3; r++)
                #pragma unroll
                for (int c = 0; c < 6; c++)
                    rin[r][c] = s_in[ci][ty + r][tx4 + c];
            #pragma unroll
            for (int ko = 0; ko < 8; ko++) {
                #pragma unroll
                for (int r = 0; r < 3; r++)
                    #pragma unroll
                    for (int cc = 0; cc < 3; cc++) {
                        float wv = s_w[ko][ci][r*3 + cc];
                        #pragma unroll
                        for (int p = 0; p < 4; p++)
                            acc[p][ko] = fmaf(rin[r][p + cc], wv, acc[p][ko]);
                    }
            }
        }
        __syncthreads();
    }

    // epilogue
    const int orow = row0 + ty;
    #pragma unroll
    for (int ko = 0; ko < 8; ko++) {
        const int oc = kog*8 + ko;
        const float s = scale[oc];
        const float b = bias[oc];
        float gmul = 1.f;
        if (MODE == 0) gmul = gate_or_res[cam*256 + oc];
        #pragma unroll
        for (int p = 0; p < 4; p++) {
            const int ocol = col0 + tx4 + p;
            if (ocol < WW) {
                const size_t oidx = (size_t)cam*MID*NPIX + (size_t)oc*NPIX + orow*WW + ocol;
                float v = acc[p][ko] * s + b;
                if (MODE == 0)      v = fmaxf(v, 0.f) * gmul;
                else if (MODE == 1) v = fmaxf(v, 0.f);
                else                v = fmaxf(v + gate_or_res[oidx], 0.f);
                out[oidx] = v;
            }
        }
    }
}

// ---------------- 1x1 depth conv + softmax over 112 bins ----------------
__global__ __launch_bounds__(128)
void depth_softmax_kernel(const float* __restrict__ x,   // [6][256][2816]
                          const float* __restrict__ w,   // [112][256]
                          const float* __restrict__ b,   // [112]
                          float* __restrict__ dp)        // [6][112][2816]
{
    const int pix = blockIdx.x;           // cam*2816 + p
    const int cam = pix / NPIX;
    const int p   = pix % NPIX;
    const int tid = threadIdx.x;          // 128

    __shared__ float sx[256];
    __shared__ float red[128];

    const float* xc = x + (size_t)cam*MID*NPIX + p;
    sx[tid]       = xc[(size_t)tid       * NPIX];
    sx[tid + 128] = xc[(size_t)(tid+128) * NPIX];
    __syncthreads();

    float lg = -1e30f;
    if (tid < DBINS) {
        float s = b[tid];
        const float* wr = w + tid*256;
        #pragma unroll 8
        for (int c = 0; c < 256; c++) s = fmaf(sx[c], wr[c], s);
        lg = s;
    }
    red[tid] = lg; __syncthreads();
    for (int off = 64; off > 0; off >>= 1) {
        if (tid < off) red[tid] = fmaxf(red[tid], red[tid + off]);
        __syncthreads();
    }
    const float m = red[0];
    __syncthreads();

    float e = (tid < DBINS) ? __expf(lg - m) : 0.f;
    red[tid] = e; __syncthreads();
    for (int off = 64; off > 0; off >>= 1) {
        if (tid < off) red[tid] += red[tid + off];
        __syncthreads();
    }
    const float inv = 1.f / red[0];
    if (tid < DBINS)
        dp[((size_t)cam*DBINS + tid) * NPIX + p] = e * inv;
}

// ---------------- trilinear grid-sample + cam-sum + mask-normalize ----------------
__global__ __launch_bounds__(256)
void sample_kernel(const float* __restrict__ grid,   // [6][128][128][16][3]
                   const float* __restrict__ dp,     // [6][112][32][88]
                   float* __restrict__ out)          // [262144]
{
    const int v = blockIdx.x * blockDim.x + threadIdx.x;
    if (v >= NVOX) return;

    float agg = 0.f, mask = 0.f;
    #pragma unroll 1
    for (int cam = 0; cam < NCAM; cam++) {
        const float* g = grid + ((size_t)cam * NVOX + v) * 3;
        const float gx = g[0], gy = g[1], gz = g[2];
        const float ix = ((gx + 1.f) * 88.f  - 1.f) * 0.5f;
        const float iy = ((gy + 1.f) * 32.f  - 1.f) * 0.5f;
        const float iz = ((gz + 1.f) * 112.f - 1.f) * 0.5f;
        const float fx0 = floorf(ix), fy0 = floorf(iy), fz0 = floorf(iz);
        const float fx = ix - fx0, fy = iy - fy0, fz = iz - fz0;
        const int x0 = (int)fx0, y0 = (int)fy0, z0 = (int)fz0;
        const float* dc = dp + (size_t)cam * DBINS * NPIX;
        #pragma unroll
        for (int dz = 0; dz < 2; dz++)
            #pragma unroll
            for (int dy = 0; dy < 2; dy++)
                #pragma unroll
                for (int dx = 0; dx < 2; dx++) {
                    const int xi = x0 + dx, yi = y0 + dy, zi = z0 + dz;
                    const float wv = (dx ? fx : 1.f - fx) * (dy ? fy : 1.f - fy) * (dz ? fz : 1.f - fz);
                    if (xi >= 0 && xi < WW && yi >= 0 && yi < HH && zi >= 0 && zi < DBINS) {
                        agg  += wv * dc[(size_t)zi * NPIX + yi*WW + xi];
                        mask += wv;
                    }
                }
    }
    out[v] = (mask > 0.f) ? (agg / mask) : agg;
}

// ---------------- launch ----------------
extern "C" void kernel_launch(void* const* d_in, const int* in_sizes, int n_in,
                              void* d_out, int out_size)
{
    const float* img    = (const float*)d_in[0];
    const float* intr   = (const float*)d_in[1];
    const float* grid   = (const float*)d_in[2];
    const float* red_w  = (const float*)d_in[3];
    const float* red_s  = (const float*)d_in[4];
    const float* red_b  = (const float*)d_in[5];
    const float* mlp_w1 = (const float*)d_in[6];
    const float* mlp_b1 = (const float*)d_in[7];
    const float* mlp_w2 = (const float*)d_in[8];
    const float* mlp_b2 = (const float*)d_in[9];
    const float* se_rw  = (const float*)d_in[10];
    const float* se_rb  = (const float*)d_in[11];
    const float* se_ew  = (const float*)d_in[12];
    const float* se_eb  = (const float*)d_in[13];
    const float* bb_w   = (const float*)d_in[14];
    const float* bb_s   = (const float*)d_in[15];
    const float* bb_b   = (const float*)d_in[16];
    const float* dp_w   = (const float*)d_in[17];
    const float* dp_b   = (const float*)d_in[18];

    float *px, *py, *pdp, *pg;
    cudaGetSymbolAddress((void**)&px,  g_x);
    cudaGetSymbolAddress((void**)&py,  g_y);
    cudaGetSymbolAddress((void**)&pdp, g_dp);
    cudaGetSymbolAddress((void**)&pg,  g_gate);

    // 1) SE gate
    gate_kernel<<<NCAM, 256>>>(intr, mlp_w1, mlp_b1, mlp_w2, mlp_b2,
                               se_rw, se_rb, se_ew, se_eb, pg);

    // 2) reduce conv 512->256 (+scale/bias/relu, *gate)
    dim3 cgrid(3, 4, NCAM * 32);
    conv3x3_kernel<CIN_IMG, 0><<<cgrid, 64>>>(img, red_w, red_s, red_b, pg, px);

    // 3) three residual blocks
    const size_t WSTEP = (size_t)MID * MID * 9;
    for (int i = 0; i < 3; i++) {
        conv3x3_kernel<MID, 1><<<cgrid, 64>>>(px, bb_w + (size_t)(2*i)   * WSTEP,
                                              bb_s + (2*i)*MID,   bb_b + (2*i)*MID,
                                              nullptr, py);
        conv3x3_kernel<MID, 2><<<cgrid, 64>>>(py, bb_w + (size_t)(2*i+1) * WSTEP,
                                              bb_s + (2*i+1)*MID, bb_b + (2*i+1)*MID,
                                              px, px);
    }

    // 4) depth head + softmax
    depth_softmax_kernel<<<NCAM * NPIX, 128>>>(px, dp_w, dp_b, pdp);

    // 5) trilinear sample + camera sum + normalize
    sample_kernel<<<(NVOX + 255) / 256, 256>>>(grid, pdp, (float*)d_out);
}

// round 2
// speedup vs baseline: 1.1329x; 1.1329x over previous
#include <cuda_runtime.h>
#include <cuda_bf16.h>
#include <math.h>

#define NCAM 6
#define CIN_IMG 512
#define MID 256
#define DBINS 112
#define HH 32
#define WW 88
#define NPIX (HH*WW)          // 2816
#define NVOX (128*128*16)     // 262144

// ---------------- device scratch (no allocations allowed) ----------------
__device__ float g_x [NCAM*MID*NPIX];     // 17.3 MB
__device__ float g_y [NCAM*MID*NPIX];     // 17.3 MB
__device__ float g_dp[NCAM*DBINS*NPIX];   //  7.6 MB
__device__ float g_gate[NCAM*MID];

// packed f32x2 FMA (sm_103a): d = a*b + d, two fp32 lanes per issue slot
__device__ __forceinline__ void fma2(float2 &d, const float2 &a, const float2 &b) {
    unsigned long long &dd = reinterpret_cast<unsigned long long&>(const_cast<float2&>(d));
    const unsigned long long aa = reinterpret_cast<const unsigned long long&>(a);
    const unsigned long long bb = reinterpret_cast<const unsigned long long&>(b);
    asm("fma.rn.f32x2 %0, %1, %2, %0;" : "+l"(dd) : "l"(aa), "l"(bb));
}

// ---------------- gate / SE path (tiny) ----------------
__global__ void gate_kernel(const float* __restrict__ intr,
                            const float* __restrict__ w1, const float* __restrict__ b1,
                            const float* __restrict__ w2, const float* __restrict__ b2,
                            const float* __restrict__ rw, const float* __restrict__ rb,
                            const float* __restrict__ ew, const float* __restrict__ eb,
                            float* __restrict__ gate)
{
    int cam = blockIdx.x;
    int tid = threadIdx.x;   // 256
    __shared__ float sp_s;
    __shared__ float h[256], h2[256], t[256];

    if (tid == 0) {
        double A[4][8];
        for (int r = 0; r < 4; r++) {
            for (int c = 0; c < 4; c++) A[r][c] = (double)intr[cam*16 + r*4 + c];
            for (int c = 0; c < 4; c++) A[r][4+c] = (r == c) ? 1.0 : 0.0;
        }
        for (int col = 0; col < 4; col++) {
            int piv = col; double best = fabs(A[col][col]);
            for (int r = col+1; r < 4; r++)
                if (fabs(A[r][col]) > best) { best = fabs(A[r][col]); piv = r; }
            if (piv != col)
                for (int c = 0; c < 8; c++) { double tmp = A[col][c]; A[col][c] = A[piv][c]; A[piv][c] = tmp; }
            double d = A[col][col];
            for (int c = 0; c < 8; c++) A[col][c] /= d;
            for (int r = 0; r < 4; r++) if (r != col) {
                double f = A[r][col];
                for (int c = 0; c < 8; c++) A[r][c] -= f * A[col][c];
            }
        }
        double i00 = A[0][4], i11 = A[1][5];
        sp_s = (float)(1000.0 * sqrt(i00*i00 + i11*i11));
    }
    __syncthreads();
    float sp = sp_s;

    h[tid] = fmaxf(sp * w1[tid] + b1[tid], 0.f);
    __syncthreads();

    float s = b2[tid];
    for (int k = 0; k < 256; k++) s += h[k] * w2[k*256 + tid];
    h2[tid] = s;
    __syncthreads();

    s = rb[tid];
    for (int c = 0; c < 256; c++) s += rw[tid*256 + c] * h2[c];
    t[tid] = fmaxf(s, 0.f);
    __syncthreads();

    s = eb[tid];
    for (int c = 0; c < 256; c++) s += ew[tid*256 + c] * t[c];
    gate[cam*256 + tid] = 1.f / (1.f + __expf(-s));
}

// ---------------- 3x3 conv, direct, f32x2-packed ----------------
// Block: 128 threads = 4 warps. Warp og computes oc (kog*32 + og*8 .. +7).
// Thread (ty,tx): row row0+ty, cols col0 + tx*8 .. +7  (8 px, as 4 f32x2 pairs).
// MODE 0: out = relu(conv*s+b) * gate[cam][oc]
// MODE 1: out = relu(conv*s+b)
// MODE 2: out = relu(res + conv*s+b)
template<int CIN, int MODE>
__global__ __launch_bounds__(128)
void conv3x3_kernel(const float* __restrict__ in,          // [6][CIN][32][88]
                    const float* __restrict__ wgt,         // [256][CIN][3][3]
                    const float* __restrict__ scale,       // [256]
                    const float* __restrict__ bias,        // [256]
                    const float* __restrict__ gate_or_res,
                    float* __restrict__ out)               // [6][256][32][88]
{
    const int ct   = blockIdx.x;          // col tile: col0 = ct*32
    const int rt   = blockIdx.y;          // row tile: row0 = rt*8
    const int cam  = blockIdx.z >> 3;
    const int kog  = blockIdx.z & 7;      // oc group of 32: base kog*32
    const int tid  = threadIdx.x;         // 128
    const int og   = tid >> 5;            // warp id = 8-oc subgroup
    const int lane = tid & 31;
    const int ty   = lane >> 2;           // 0..7 rows
    const int tx   = lane & 3;            // 0..3 -> cols tx*8..+7

    __shared__ __align__(16) float  s_in[8][10][34];   // [ci][r][c]  (stride 34: conflict-free LDS.64)
    __shared__ __align__(16) float2 s_w [32][8][9];    // [ko][ci][tap], duplicated (w,w)

    const int row0 = rt * 8;
    const int col0 = ct * 32;

    float2 acc[8][4];
    #pragma unroll
    for (int k = 0; k < 8; k++)
        #pragma unroll
        for (int p = 0; p < 4; p++) acc[k][p] = make_float2(0.f, 0.f);

    const float* inc = in  + cam * CIN * NPIX;
    const float* wc  = wgt + (kog*32) * CIN * 9;

    for (int ci0 = 0; ci0 < CIN; ci0 += 8) {
        // ---- cooperative loads ----
        const float* ip = inc + ci0 * NPIX;
        for (int idx = tid; idx < 8*10*34; idx += 128) {
            const int ci  = idx / 340;
            const int rem = idx - ci*340;
            const int r   = rem / 34;
            const int c   = rem - r*34;
            const int gh = row0 - 1 + r;
            const int gw = col0 - 1 + c;
            float v = 0.f;
            if (gh >= 0 && gh < HH && gw >= 0 && gw < WW)
                v = ip[ci * NPIX + gh*WW + gw];
            s_in[ci][r][c] = v;
        }
        for (int idx = tid; idx < 32*8*9; idx += 128) {      // 18 iters
            const int ko  = idx / 72;
            const int rem = idx - ko*72;
            const int ci  = rem / 9;
            const int tap = rem - ci*9;
            const float w = wc[ko * CIN * 9 + (ci0 + ci) * 9 + tap];
            s_w[ko][ci][tap] = make_float2(w, w);
        }
        __syncthreads();

        // ---- compute ----
        #pragma unroll
        for (int ci = 0; ci < 8; ci++) {
            #pragma unroll
            for (int r = 0; r < 3; r++) {
                // 10 input floats as 5 aligned pairs
                float2 v[5];
                const float* rowp = &s_in[ci][ty + r][tx * 8];
                #pragma unroll
                for (int j = 0; j < 5; j++)
                    v[j] = *reinterpret_cast<const float2*>(rowp + 2*j);
                // misaligned pairs for center tap
                float2 m[4];
                #pragma unroll
                for (int p = 0; p < 4; p++)
                    m[p] = make_float2(v[p].y, v[p+1].x);

                #pragma unroll
                for (int ko = 0; ko < 8; ko++) {
                    const float2* wp = &s_w[og*8 + ko][ci][r*3];
                    const float2 w0 = wp[0], w1 = wp[1], w2 = wp[2];
                    #pragma unroll
                    for (int p = 0; p < 4; p++) {
                        fma2(acc[ko][p], v[p],   w0);
                        fma2(acc[ko][p], m[p],   w1);
                        fma2(acc[ko][p], v[p+1], w2);
                    }
                }
            }
        }
        __syncthreads();
    }

    // ---- epilogue ----
    const int orow = row0 + ty;
    #pragma unroll
    for (int ko = 0; ko < 8; ko++) {
        const int oc = kog*32 + og*8 + ko;
        const float s = scale[oc];
        const float b = bias[oc];
        float gmul = 1.f;
        if (MODE == 0) gmul = gate_or_res[cam*256 + oc];
        #pragma unroll
        for (int p = 0; p < 4; p++) {
            const int ocol = col0 + tx*8 + 2*p;          // even; pair fully in/out (WW even)
            if (ocol < WW) {
                const int oidx = cam*MID*NPIX + oc*NPIX + orow*WW + ocol;
                float vx = acc[ko][p].x * s + b;
                float vy = acc[ko][p].y * s + b;
                if (MODE == 0) {
                    vx = fmaxf(vx, 0.f) * gmul;
                    vy = fmaxf(vy, 0.f) * gmul;
                } else if (MODE == 1) {
                    vx = fmaxf(vx, 0.f);
                    vy = fmaxf(vy, 0.f);
                } else {
                    const float2 res = *reinterpret_cast<const float2*>(&gate_or_res[oidx]);
                    vx = fmaxf(vx + res.x, 0.f);
                    vy = fmaxf(vy + res.y, 0.f);
                }
                *reinterpret_cast<float2*>(&out[oidx]) = make_float2(vx, vy);
            }
        }
    }
}

// ---------------- 1x1 depth conv + softmax over 112 bins ----------------
__global__ __launch_bounds__(128)
void depth_softmax_kernel(const float* __restrict__ x,   // [6][256][2816]
                          const float* __restrict__ w,   // [112][256]
                          const float* __restrict__ b,   // [112]
                          float* __restrict__ dp)        // [6][112][2816]
{
    const int pix = blockIdx.x;           // cam*2816 + p
    const int cam = pix / NPIX;
    const int p   = pix % NPIX;
    const int tid = threadIdx.x;          // 128

    __shared__ float sx[256];
    __shared__ float red[128];

    const float* xc = x + cam*MID*NPIX + p;
    sx[tid]       = xc[tid       * NPIX];
    sx[tid + 128] = xc[(tid+128) * NPIX];
    __syncthreads();

    float lg = -1e30f;
    if (tid < DBINS) {
        float s = b[tid];
        const float* wr = w + tid*256;
        #pragma unroll 8
        for (int c = 0; c < 256; c++) s = fmaf(sx[c], wr[c], s);
        lg = s;
    }
    red[tid] = lg; __syncthreads();
    for (int off = 64; off > 0; off >>= 1) {
        if (tid < off) red[tid] = fmaxf(red[tid], red[tid + off]);
        __syncthreads();
    }
    const float m = red[0];
    __syncthreads();

    float e = (tid < DBINS) ? __expf(lg - m) : 0.f;
    red[tid] = e; __syncthreads();
    for (int off = 64; off > 0; off >>= 1) {
        if (tid < off) red[tid] += red[tid + off];
        __syncthreads();
    }
    const float inv = 1.f / red[0];
    if (tid < DBINS)
        dp[(cam*DBINS + tid) * NPIX + p] = e * inv;
}

// ---------------- trilinear grid-sample + cam-sum + mask-normalize ----------------
__global__ __launch_bounds__(256)
void sample_kernel(const float* __restrict__ grid,   // [6][128][128][16][3]
                   const float* __restrict__ dp,     // [6][112][32][88]
                   float* __restrict__ out)          // [262144]
{
    const int v = blockIdx.x * blockDim.x + threadIdx.x;
    if (v >= NVOX) return;

    float agg = 0.f, mask = 0.f;
    #pragma unroll 1
    for (int cam = 0; cam < NCAM; cam++) {
        const float* g = grid + ((size_t)cam * NVOX + v) * 3;
        const float gx = g[0], gy = g[1], gz = g[2];
        const float ix = ((gx + 1.f) * 88.f  - 1.f) * 0.5f;
        const float iy = ((gy + 1.f) * 32.f  - 1.f) * 0.5f;
        const float iz = ((gz + 1.f) * 112.f - 1.f) * 0.5f;
        const float fx0 = floorf(ix), fy0 = floorf(iy), fz0 = floorf(iz);
        const float fx = ix - fx0, fy = iy - fy0, fz = iz - fz0;
        const int x0 = (int)fx0, y0 = (int)fy0, z0 = (int)fz0;
        const float* dc = dp + cam * DBINS * NPIX;
        #pragma unroll
        for (int dz = 0; dz < 2; dz++)
            #pragma unroll
            for (int dy = 0; dy < 2; dy++)
                #pragma unroll
                for (int dx = 0; dx < 2; dx++) {
                    const int xi = x0 + dx, yi = y0 + dy, zi = z0 + dz;
                    const float wv = (dx ? fx : 1.f - fx) * (dy ? fy : 1.f - fy) * (dz ? fz : 1.f - fz);
                    if (xi >= 0 && xi < WW && yi >= 0 && yi < HH && zi >= 0 && zi < DBINS) {
                        agg  += wv * dc[zi * NPIX + yi*WW + xi];
                        mask += wv;
                    }
                }
    }
    out[v] = (mask > 0.f) ? (agg / mask) : agg;
}

// ---------------- launch ----------------
extern "C" void kernel_launch(void* const* d_in, const int* in_sizes, int n_in,
                              void* d_out, int out_size)
{
    const float* img    = (const float*)d_in[0];
    const float* intr   = (const float*)d_in[1];
    const float* grid   = (const float*)d_in[2];
    const float* red_w  = (const float*)d_in[3];
    const float* red_s  = (const float*)d_in[4];
    const float* red_b  = (const float*)d_in[5];
    const float* mlp_w1 = (const float*)d_in[6];
    const float* mlp_b1 = (const float*)d_in[7];
    const float* mlp_w2 = (const float*)d_in[8];
    const float* mlp_b2 = (const float*)d_in[9];
    const float* se_rw  = (const float*)d_in[10];
    const float* se_rb  = (const float*)d_in[11];
    const float* se_ew  = (const float*)d_in[12];
    const float* se_eb  = (const float*)d_in[13];
    const float* bb_w   = (const float*)d_in[14];
    const float* bb_s   = (const float*)d_in[15];
    const float* bb_b   = (const float*)d_in[16];
    const float* dp_w   = (const float*)d_in[17];
    const float* dp_b   = (const float*)d_in[18];

    float *px, *py, *pdp, *pg;
    cudaGetSymbolAddress((void**)&px,  g_x);
    cudaGetSymbolAddress((void**)&py,  g_y);
    cudaGetSymbolAddress((void**)&pdp, g_dp);
    cudaGetSymbolAddress((void**)&pg,  g_gate);

    // 1) SE gate
    gate_kernel<<<NCAM, 256>>>(intr, mlp_w1, mlp_b1, mlp_w2, mlp_b2,
                               se_rw, se_rb, se_ew, se_eb, pg);

    // 2) reduce conv 512->256 (+scale/bias/relu, *gate)
    dim3 cgrid(3, 4, NCAM * 8);
    conv3x3_kernel<CIN_IMG, 0><<<cgrid, 128>>>(img, red_w, red_s, red_b, pg, px);

    // 3) three residual blocks
    const size_t WSTEP = (size_t)MID * MID * 9;
    for (int i = 0; i < 3; i++) {
        conv3x3_kernel<MID, 1><<<cgrid, 128>>>(px, bb_w + (size_t)(2*i)   * WSTEP,
                                               bb_s + (2*i)*MID,   bb_b + (2*i)*MID,
                                               nullptr, py);
        conv3x3_kernel<MID, 2><<<cgrid, 128>>>(py, bb_w + (size_t)(2*i+1) * WSTEP,
                                               bb_s + (2*i+1)*MID, bb_b + (2*i+1)*MID,
                                               px, px);
    }

    // 4) depth head + softmax
    depth_softmax_kernel<<<NCAM * NPIX, 128>>>(px, dp_w, dp_b, pdp);

    // 5) trilinear sample + camera sum + normalize
    sample_kernel<<<(NVOX + 255) / 256, 256>>>(grid, pdp, (float*)d_out);
}

// round 3
// speedup vs baseline: 1.2119x; 1.0697x over previous
#include <cuda_runtime.h>
#include <cuda_bf16.h>
#include <math.h>

#define NCAM 6
#define CIN_IMG 512
#define MID 256
#define DBINS 112
#define HH 32
#define WW 88
#define NPIX (HH*WW)          // 2816
#define NVOX (128*128*16)     // 262144

// ---------------- device scratch (no allocations allowed) ----------------
__device__ float g_x [NCAM*MID*NPIX];     // 17.3 MB
__device__ float g_y [NCAM*MID*NPIX];     // 17.3 MB
__device__ float g_dp[NCAM*DBINS*NPIX];   //  7.6 MB
__device__ float g_gate[NCAM*MID];

// packed f32x2 FMA (sm_103a): d = a*b + d, two fp32 lanes per issue slot
__device__ __forceinline__ void fma2(float2 &d, const float2 &a, const float2 &b) {
    unsigned long long &dd = reinterpret_cast<unsigned long long&>(const_cast<float2&>(d));
    const unsigned long long aa = reinterpret_cast<const unsigned long long&>(a);
    const unsigned long long bb = reinterpret_cast<const unsigned long long&>(b);
    asm("fma.rn.f32x2 %0, %1, %2, %0;" : "+l"(dd) : "l"(aa), "l"(bb));
}

// ---------------- gate / SE path (tiny) ----------------
__global__ void gate_kernel(const float* __restrict__ intr,
                            const float* __restrict__ w1, const float* __restrict__ b1,
                            const float* __restrict__ w2, const float* __restrict__ b2,
                            const float* __restrict__ rw, const float* __restrict__ rb,
                            const float* __restrict__ ew, const float* __restrict__ eb,
                            float* __restrict__ gate)
{
    int cam = blockIdx.x;
    int tid = threadIdx.x;   // 256
    __shared__ float sp_s;
    __shared__ float h[256], h2[256], t[256];

    if (tid == 0) {
        double A[4][8];
        for (int r = 0; r < 4; r++) {
            for (int c = 0; c < 4; c++) A[r][c] = (double)intr[cam*16 + r*4 + c];
            for (int c = 0; c < 4; c++) A[r][4+c] = (r == c) ? 1.0 : 0.0;
        }
        for (int col = 0; col < 4; col++) {
            int piv = col; double best = fabs(A[col][col]);
            for (int r = col+1; r < 4; r++)
                if (fabs(A[r][col]) > best) { best = fabs(A[r][col]); piv = r; }
            if (piv != col)
                for (int c = 0; c < 8; c++) { double tmp = A[col][c]; A[col][c] = A[piv][c]; A[piv][c] = tmp; }
            double d = A[col][col];
            for (int c = 0; c < 8; c++) A[col][c] /= d;
            for (int r = 0; r < 4; r++) if (r != col) {
                double f = A[r][col];
                for (int c = 0; c < 8; c++) A[r][c] -= f * A[col][c];
            }
        }
        double i00 = A[0][4], i11 = A[1][5];
        sp_s = (float)(1000.0 * sqrt(i00*i00 + i11*i11));
    }
    __syncthreads();
    float sp = sp_s;

    h[tid] = fmaxf(sp * w1[tid] + b1[tid], 0.f);
    __syncthreads();

    float s = b2[tid];
    for (int k = 0; k < 256; k++) s += h[k] * w2[k*256 + tid];
    h2[tid] = s;
    __syncthreads();

    s = rb[tid];
    for (int c = 0; c < 256; c++) s += rw[tid*256 + c] * h2[c];
    t[tid] = fmaxf(s, 0.f);
    __syncthreads();

    s = eb[tid];
    for (int c = 0; c < 256; c++) s += ew[tid*256 + c] * t[c];
    gate[cam*256 + tid] = 1.f / (1.f + __expf(-s));
}

// ---------------- 3x3 conv, direct, f32x2-packed, occupancy-tuned ----------------
// Block: 128 threads = 4 warps. Warp wq computes oc (kog*16 + wq*4 .. +3).
// Thread (ty,tx): row row0+ty, cols col0 + tx*8 .. +7  (8 px, as 4 f32x2 pairs).
// MODE 0: out = relu(conv*s+b) * gate[cam][oc]
// MODE 1: out = relu(conv*s+b)
// MODE 2: out = relu(res + conv*s+b)
template<int CIN, int MODE>
__global__ __launch_bounds__(128, 6)
void conv3x3_kernel(const float* __restrict__ in,          // [6][CIN][32][88]
                    const float* __restrict__ wgt,         // [256][CIN][3][3]
                    const float* __restrict__ scale,       // [256]
                    const float* __restrict__ bias,        // [256]
                    const float* __restrict__ gate_or_res,
                    float* __restrict__ out)               // [6][256][32][88]
{
    const int ct   = blockIdx.x;          // col tile: col0 = ct*32
    const int rt   = blockIdx.y;          // row tile: row0 = rt*8
    const int cam  = blockIdx.z >> 4;
    const int kog  = blockIdx.z & 15;     // oc group of 16: base kog*16
    const int tid  = threadIdx.x;         // 128
    const int wq   = tid >> 5;            // warp id = 4-oc subgroup
    const int lane = tid & 31;
    const int ty   = lane >> 2;           // 0..7 rows
    const int tx   = lane & 3;            // 0..3 -> cols tx*8..+7

    __shared__ __align__(16) float  s_in[8][10][34];   // [ci][r][c]  (stride 34: conflict-free LDS.64)
    __shared__ __align__(16) float2 s_w [16][8][9];    // [ko][ci][tap], duplicated (w,w)

    const int row0 = rt * 8;
    const int col0 = ct * 32;

    float2 acc[4][4];
    #pragma unroll
    for (int k = 0; k < 4; k++)
        #pragma unroll
        for (int p = 0; p < 4; p++) acc[k][p] = make_float2(0.f, 0.f);

    const float* inc = in  + cam * CIN * NPIX;
    const float* wc  = wgt + (kog*16) * CIN * 9;

    for (int ci0 = 0; ci0 < CIN; ci0 += 8) {
        // ---- cooperative loads ----
        const float* ip = inc + ci0 * NPIX;
        for (int idx = tid; idx < 8*10*34; idx += 128) {
            const int ci  = idx / 340;
            const int rem = idx - ci*340;
            const int r   = rem / 34;
            const int c   = rem - r*34;
            const int gh = row0 - 1 + r;
            const int gw = col0 - 1 + c;
            float v = 0.f;
            if (gh >= 0 && gh < HH && gw >= 0 && gw < WW)
                v = ip[ci * NPIX + gh*WW + gw];
            s_in[ci][r][c] = v;
        }
        #pragma unroll
        for (int j = 0; j < 9; j++) {                    // 16*8*9 = 1152 elems
            const int idx = tid + 128*j;
            const int ko  = idx / 72;
            const int rem = idx - ko*72;
            const float w = wc[ko * CIN * 9 + ci0 * 9 + rem];
            s_w[ko][0][rem] = make_float2(w, w);         // [8][9] contiguous: flat rem
        }
        __syncthreads();

        // ---- compute ----
        #pragma unroll
        for (int ci = 0; ci < 8; ci++) {
            #pragma unroll
            for (int r = 0; r < 3; r++) {
                // 10 input floats as 5 aligned pairs
                float2 v[5];
                const float* rowp = &s_in[ci][ty + r][tx * 8];
                #pragma unroll
                for (int j = 0; j < 5; j++)
                    v[j] = *reinterpret_cast<const float2*>(rowp + 2*j);
                // misaligned pairs for center tap
                float2 m[4];
                #pragma unroll
                for (int p = 0; p < 4; p++)
                    m[p] = make_float2(v[p].y, v[p+1].x);

                #pragma unroll
                for (int ko = 0; ko < 4; ko++) {
                    const float2* wp = &s_w[wq*4 + ko][ci][r*3];
                    const float2 w0 = wp[0], w1 = wp[1], w2 = wp[2];
                    #pragma unroll
                    for (int p = 0; p < 4; p++) {
                        fma2(acc[ko][p], v[p],   w0);
                        fma2(acc[ko][p], m[p],   w1);
                        fma2(acc[ko][p], v[p+1], w2);
                    }
                }
            }
        }
        __syncthreads();
    }

    // ---- epilogue ----
    const int orow = row0 + ty;
    #pragma unroll
    for (int ko = 0; ko < 4; ko++) {
        const int oc = kog*16 + wq*4 + ko;
        const float s = scale[oc];
        const float b = bias[oc];
        float gmul = 1.f;
        if (MODE == 0) gmul = gate_or_res[cam*256 + oc];
        #pragma unroll
        for (int p = 0; p < 4; p++) {
            const int ocol = col0 + tx*8 + 2*p;          // even; pair fully in/out (WW even)
            if (ocol < WW) {
                const int oidx = cam*MID*NPIX + oc*NPIX + orow*WW + ocol;
                float vx = acc[ko][p].x * s + b;
                float vy = acc[ko][p].y * s + b;
                if (MODE == 0) {
                    vx = fmaxf(vx, 0.f) * gmul;
                    vy = fmaxf(vy, 0.f) * gmul;
                } else if (MODE == 1) {
                    vx = fmaxf(vx, 0.f);
                    vy = fmaxf(vy, 0.f);
                } else {
                    const float2 res = *reinterpret_cast<const float2*>(&gate_or_res[oidx]);
                    vx = fmaxf(vx + res.x, 0.f);
                    vy = fmaxf(vy + res.y, 0.f);
                }
                *reinterpret_cast<float2*>(&out[oidx]) = make_float2(vx, vy);
            }
        }
    }
}

// ---------------- 1x1 depth conv + softmax over 112 bins ----------------
__global__ __launch_bounds__(128)
void depth_softmax_kernel(const float* __restrict__ x,   // [6][256][2816]
                          const float* __restrict__ w,   // [112][256]
                          const float* __restrict__ b,   // [112]
                          float* __restrict__ dp)        // [6][112][2816]
{
    const int pix = blockIdx.x;           // cam*2816 + p
    const int cam = pix / NPIX;
    const int p   = pix % NPIX;
    const int tid = threadIdx.x;          // 128

    __shared__ float sx[256];
    __shared__ float red[128];

    const float* xc = x + cam*MID*NPIX + p;
    sx[tid]       = xc[tid       * NPIX];
    sx[tid + 128] = xc[(tid+128) * NPIX];
    __syncthreads();

    float lg = -1e30f;
    if (tid < DBINS) {
        float s = b[tid];
        const float* wr = w + tid*256;
        #pragma unroll 8
        for (int c = 0; c < 256; c++) s = fmaf(sx[c], wr[c], s);
        lg = s;
    }
    red[tid] = lg; __syncthreads();
    for (int off = 64; off > 0; off >>= 1) {
        if (tid < off) red[tid] = fmaxf(red[tid], red[tid + off]);
        __syncthreads();
    }
    const float m = red[0];
    __syncthreads();

    float e = (tid < DBINS) ? __expf(lg - m) : 0.f;
    red[tid] = e; __syncthreads();
    for (int off = 64; off > 0; off >>= 1) {
        if (tid < off) red[tid] += red[tid + off];
        __syncthreads();
    }
    const float inv = 1.f / red[0];
    if (tid < DBINS)
        dp[(cam*DBINS + tid) * NPIX + p] = e * inv;
}

// ---------------- trilinear grid-sample + cam-sum + mask-normalize ----------------
__global__ __launch_bounds__(256)
void sample_kernel(const float* __restrict__ grid,   // [6][128][128][16][3]
                   const float* __restrict__ dp,     // [6][112][32][88]
                   float* __restrict__ out)          // [262144]
{
    const int v = blockIdx.x * blockDim.x + threadIdx.x;
    if (v >= NVOX) return;

    float agg = 0.f, mask = 0.f;
    #pragma unroll 1
    for (int cam = 0; cam < NCAM; cam++) {
        const float* g = grid + ((size_t)cam * NVOX + v) * 3;
        const float gx = g[0], gy = g[1], gz = g[2];
        const float ix = ((gx + 1.f) * 88.f  - 1.f) * 0.5f;
        const float iy = ((gy + 1.f) * 32.f  - 1.f) * 0.5f;
        const float iz = ((gz + 1.f) * 112.f - 1.f) * 0.5f;
        const float fx0 = floorf(ix), fy0 = floorf(iy), fz0 = floorf(iz);
        const float fx = ix - fx0, fy = iy - fy0, fz = iz - fz0;
        const int x0 = (int)fx0, y0 = (int)fy0, z0 = (int)fz0;
        const float* dc = dp + cam * DBINS * NPIX;
        #pragma unroll
        for (int dz = 0; dz < 2; dz++)
            #pragma unroll
            for (int dy = 0; dy < 2; dy++)
                #pragma unroll
                for (int dx = 0; dx < 2; dx++) {
                    const int xi = x0 + dx, yi = y0 + dy, zi = z0 + dz;
                    const float wv = (dx ? fx : 1.f - fx) * (dy ? fy : 1.f - fy) * (dz ? fz : 1.f - fz);
                    if (xi >= 0 && xi < WW && yi >= 0 && yi < HH && zi >= 0 && zi < DBINS) {
                        agg  += wv * dc[zi * NPIX + yi*WW + xi];
                        mask += wv;
                    }
                }
    }
    out[v] = (mask > 0.f) ? (agg / mask) : agg;
}

// ---------------- launch ----------------
extern "C" void kernel_launch(void* const* d_in, const int* in_sizes, int n_in,
                              void* d_out, int out_size)
{
    const float* img    = (const float*)d_in[0];
    const float* intr   = (const float*)d_in[1];
    const float* grid   = (const float*)d_in[2];
    const float* red_w  = (const float*)d_in[3];
    const float* red_s  = (const float*)d_in[4];
    const float* red_b  = (const float*)d_in[5];
    const float* mlp_w1 = (const float*)d_in[6];
    const float* mlp_b1 = (const float*)d_in[7];
    const float* mlp_w2 = (const float*)d_in[8];
    const float* mlp_b2 = (const float*)d_in[9];
    const float* se_rw  = (const float*)d_in[10];
    const float* se_rb  = (const float*)d_in[11];
    const float* se_ew  = (const float*)d_in[12];
    const float* se_eb  = (const float*)d_in[13];
    const float* bb_w   = (const float*)d_in[14];
    const float* bb_s   = (const float*)d_in[15];
    const float* bb_b   = (const float*)d_in[16];
    const float* dp_w   = (const float*)d_in[17];
    const float* dp_b   = (const float*)d_in[18];

    float *px, *py, *pdp, *pg;
    cudaGetSymbolAddress((void**)&px,  g_x);
    cudaGetSymbolAddress((void**)&py,  g_y);
    cudaGetSymbolAddress((void**)&pdp, g_dp);
    cudaGetSymbolAddress((void**)&pg,  g_gate);

    // 1) SE gate
    gate_kernel<<<NCAM, 256>>>(intr, mlp_w1, mlp_b1, mlp_w2, mlp_b2,
                               se_rw, se_rb, se_ew, se_eb, pg);

    // 2) reduce conv 512->256 (+scale/bias/relu, *gate)
    dim3 cgrid(3, 4, NCAM * 16);
    conv3x3_kernel<CIN_IMG, 0><<<cgrid, 128>>>(img, red_w, red_s, red_b, pg, px);

    // 3) three residual blocks
    const size_t WSTEP = (size_t)MID * MID * 9;
    for (int i = 0; i < 3; i++) {
        conv3x3_kernel<MID, 1><<<cgrid, 128>>>(px, bb_w + (size_t)(2*i)   * WSTEP,
                                               bb_s + (2*i)*MID,   bb_b + (2*i)*MID,
                                               nullptr, py);
        conv3x3_kernel<MID, 2><<<cgrid, 128>>>(py, bb_w + (size_t)(2*i+1) * WSTEP,
                                               bb_s + (2*i+1)*MID, bb_b + (2*i+1)*MID,
                                               px, px);
    }

    // 4) depth head + softmax
    depth_softmax_kernel<<<NCAM * NPIX, 128>>>(px, dp_w, dp_b, pdp);

    // 5) trilinear sample + camera sum + normalize
    sample_kernel<<<(NVOX + 255) / 256, 256>>>(grid, pdp, (float*)d_out);
}

// round 4
// speedup vs baseline: 1.2122x; 1.0002x over previous
#include <cuda_runtime.h>
#include <cuda_bf16.h>
#include <math.h>

#define NCAM 6
#define CIN_IMG 512
#define MID 256
#define DBINS 112
#define HH 32
#define WW 88
#define NPIX (HH*WW)          // 2816
#define NVOX (128*128*16)     // 262144

// ---------------- device scratch (no allocations allowed) ----------------
__device__ float g_x [NCAM*MID*NPIX];     // 17.3 MB
__device__ float g_y [NCAM*MID*NPIX];     // 17.3 MB
__device__ float g_dp[NCAM*DBINS*NPIX];   //  7.6 MB
__device__ float g_gate[NCAM*MID];

// packed f32x2 FMA (sm_103a): d = a*b + d, two fp32 lanes per issue slot
__device__ __forceinline__ void fma2(float2 &d, const float2 &a, const float2 &b) {
    unsigned long long &dd = reinterpret_cast<unsigned long long&>(const_cast<float2&>(d));
    const unsigned long long aa = reinterpret_cast<const unsigned long long&>(a);
    const unsigned long long bb = reinterpret_cast<const unsigned long long&>(b);
    asm("fma.rn.f32x2 %0, %1, %2, %0;" : "+l"(dd) : "l"(aa), "l"(bb));
}

// ---------------- gate / SE path (tiny) ----------------
__global__ void gate_kernel(const float* __restrict__ intr,
                            const float* __restrict__ w1, const float* __restrict__ b1,
                            const float* __restrict__ w2, const float* __restrict__ b2,
                            const float* __restrict__ rw, const float* __restrict__ rb,
                            const float* __restrict__ ew, const float* __restrict__ eb,
                            float* __restrict__ gate)
{
    int cam = blockIdx.x;
    int tid = threadIdx.x;   // 256
    __shared__ float sp_s;
    __shared__ float h[256], h2[256], t[256];

    if (tid == 0) {
        double A[4][8];
        for (int r = 0; r < 4; r++) {
            for (int c = 0; c < 4; c++) A[r][c] = (double)intr[cam*16 + r*4 + c];
            for (int c = 0; c < 4; c++) A[r][4+c] = (r == c) ? 1.0 : 0.0;
        }
        for (int col = 0; col < 4; col++) {
            int piv = col; double best = fabs(A[col][col]);
            for (int r = col+1; r < 4; r++)
                if (fabs(A[r][col]) > best) { best = fabs(A[r][col]); piv = r; }
            if (piv != col)
                for (int c = 0; c < 8; c++) { double tmp = A[col][c]; A[col][c] = A[piv][c]; A[piv][c] = tmp; }
            double d = A[col][col];
            for (int c = 0; c < 8; c++) A[col][c] /= d;
            for (int r = 0; r < 4; r++) if (r != col) {
                double f = A[r][col];
                for (int c = 0; c < 8; c++) A[r][c] -= f * A[col][c];
            }
        }
        double i00 = A[0][4], i11 = A[1][5];
        sp_s = (float)(1000.0 * sqrt(i00*i00 + i11*i11));
    }
    __syncthreads();
    float sp = sp_s;

    h[tid] = fmaxf(sp * w1[tid] + b1[tid], 0.f);
    __syncthreads();

    float s = b2[tid];
    for (int k = 0; k < 256; k++) s += h[k] * w2[k*256 + tid];
    h2[tid] = s;
    __syncthreads();

    s = rb[tid];
    for (int c = 0; c < 256; c++) s += rw[tid*256 + c] * h2[c];
    t[tid] = fmaxf(s, 0.f);
    __syncthreads();

    s = eb[tid];
    for (int c = 0; c < 256; c++) s += ew[tid*256 + c] * t[c];
    gate[cam*256 + tid] = 1.f / (1.f + __expf(-s));
}

// ---------------- 3x3 conv, direct, f32x2-packed, occupancy-tuned ----------------
// Block: 128 threads = 4 warps. Warp wq computes oc (kog*16 + wq*4 .. +3).
// Thread (ty,tx): row row0+ty, cols col0 + tx*8 .. +7  (8 px, as 4 f32x2 pairs).
// MODE 0: out = relu(conv*s+b) * gate[cam][oc]
// MODE 1: out = relu(conv*s+b)
// MODE 2: out = relu(res + conv*s+b)
template<int CIN, int MODE>
__global__ __launch_bounds__(128, 6)
void conv3x3_kernel(const float* __restrict__ in,          // [6][CIN][32][88]
                    const float* __restrict__ wgt,         // [256][CIN][3][3]
                    const float* __restrict__ scale,       // [256]
                    const float* __restrict__ bias,        // [256]
                    const float* __restrict__ gate_or_res,
                    float* __restrict__ out)               // [6][256][32][88]
{
    const int ct   = blockIdx.x;          // col tile: col0 = ct*32
    const int rt   = blockIdx.y;          // row tile: row0 = rt*8
    const int cam  = blockIdx.z >> 4;
    const int kog  = blockIdx.z & 15;     // oc group of 16: base kog*16
    const int tid  = threadIdx.x;         // 128
    const int wq   = tid >> 5;            // warp id = 4-oc subgroup
    const int lane = tid & 31;
    const int ty   = lane >> 2;           // 0..7 rows
    const int tx   = lane & 3;            // 0..3 -> cols tx*8..+7

    __shared__ __align__(16) float  s_in[8][10][34];   // [ci][r][c]  (stride 34: conflict-free LDS.64)
    __shared__ __align__(16) float2 s_w [16][8][9];    // [ko][ci][tap], duplicated (w,w)

    const int row0 = rt * 8;
    const int col0 = ct * 32;

    float2 acc[4][4];
    #pragma unroll
    for (int k = 0; k < 4; k++)
        #pragma unroll
        for (int p = 0; p < 4; p++) acc[k][p] = make_float2(0.f, 0.f);

    const float* inc = in  + cam * CIN * NPIX;
    const float* wc  = wgt + (kog*16) * CIN * 9;

    for (int ci0 = 0; ci0 < CIN; ci0 += 8) {
        // ---- cooperative loads ----
        const float* ip = inc + ci0 * NPIX;
        for (int idx = tid; idx < 8*10*34; idx += 128) {
            const int ci  = idx / 340;
            const int rem = idx - ci*340;
            const int r   = rem / 34;
            const int c   = rem - r*34;
            const int gh = row0 - 1 + r;
            const int gw = col0 - 1 + c;
            float v = 0.f;
            if (gh >= 0 && gh < HH && gw >= 0 && gw < WW)
                v = ip[ci * NPIX + gh*WW + gw];
            s_in[ci][r][c] = v;
        }
        #pragma unroll
        for (int j = 0; j < 9; j++) {                    // 16*8*9 = 1152 elems
            const int idx = tid + 128*j;
            const int ko  = idx / 72;
            const int rem = idx - ko*72;
            const float w = wc[ko * CIN * 9 + ci0 * 9 + rem];
            s_w[ko][0][rem] = make_float2(w, w);         // [8][9] contiguous: flat rem
        }
        __syncthreads();

        // ---- compute ----
        #pragma unroll
        for (int ci = 0; ci < 8; ci++) {
            #pragma unroll
            for (int r = 0; r < 3; r++) {
                // 10 input floats as 5 aligned pairs
                float2 v[5];
                const float* rowp = &s_in[ci][ty + r][tx * 8];
                #pragma unroll
                for (int j = 0; j < 5; j++)
                    v[j] = *reinterpret_cast<const float2*>(rowp + 2*j);
                // misaligned pairs for center tap
                float2 m[4];
                #pragma unroll
                for (int p = 0; p < 4; p++)
                    m[p] = make_float2(v[p].y, v[p+1].x);

                #pragma unroll
                for (int ko = 0; ko < 4; ko++) {
                    const float2* wp = &s_w[wq*4 + ko][ci][r*3];
                    const float2 w0 = wp[0], w1 = wp[1], w2 = wp[2];
                    #pragma unroll
                    for (int p = 0; p < 4; p++) {
                        fma2(acc[ko][p], v[p],   w0);
                        fma2(acc[ko][p], m[p],   w1);
                        fma2(acc[ko][p], v[p+1], w2);
                    }
                }
            }
        }
        __syncthreads();
    }

    // ---- epilogue ----
    const int orow = row0 + ty;
    #pragma unroll
    for (int ko = 0; ko < 4; ko++) {
        const int oc = kog*16 + wq*4 + ko;
        const float s = scale[oc];
        const float b = bias[oc];
        float gmul = 1.f;
        if (MODE == 0) gmul = gate_or_res[cam*256 + oc];
        #pragma unroll
        for (int p = 0; p < 4; p++) {
            const int ocol = col0 + tx*8 + 2*p;          // even; pair fully in/out (WW even)
            if (ocol < WW) {
                const int oidx = cam*MID*NPIX + oc*NPIX + orow*WW + ocol;
                float vx = acc[ko][p].x * s + b;
                float vy = acc[ko][p].y * s + b;
                if (MODE == 0) {
                    vx = fmaxf(vx, 0.f) * gmul;
                    vy = fmaxf(vy, 0.f) * gmul;
                } else if (MODE == 1) {
                    vx = fmaxf(vx, 0.f);
                    vy = fmaxf(vy, 0.f);
                } else {
                    const float2 res = *reinterpret_cast<const float2*>(&gate_or_res[oidx]);
                    vx = fmaxf(vx + res.x, 0.f);
                    vy = fmaxf(vy + res.y, 0.f);
                }
                *reinterpret_cast<float2*>(&out[oidx]) = make_float2(vx, vy);
            }
        }
    }
}

// ---------------- 1x1 depth conv + softmax over 112 bins ----------------
__global__ __launch_bounds__(128)
void depth_softmax_kernel(const float* __restrict__ x,   // [6][256][2816]
                          const float* __restrict__ w,   // [112][256]
                          const float* __restrict__ b,   // [112]
                          float* __restrict__ dp)        // [6][112][2816]
{
    const int pix = blockIdx.x;           // cam*2816 + p
    const int cam = pix / NPIX;
    const int p   = pix % NPIX;
    const int tid = threadIdx.x;          // 128

    __shared__ float sx[256];
    __shared__ float red[128];

    const float* xc = x + cam*MID*NPIX + p;
    sx[tid]       = xc[tid       * NPIX];
    sx[tid + 128] = xc[(tid+128) * NPIX];
    __syncthreads();

    float lg = -1e30f;
    if (tid < DBINS) {
        float s = b[tid];
        const float* wr = w + tid*256;
        #pragma unroll 8
        for (int c = 0; c < 256; c++) s = fmaf(sx[c], wr[c], s);
        lg = s;
    }
    red[tid] = lg; __syncthreads();
    for (int off = 64; off > 0; off >>= 1) {
        if (tid < off) red[tid] = fmaxf(red[tid], red[tid + off]);
        __syncthreads();
    }
    const float m = red[0];
    __syncthreads();

    float e = (tid < DBINS) ? __expf(lg - m) : 0.f;
    red[tid] = e; __syncthreads();
    for (int off = 64; off > 0; off >>= 1) {
        if (tid < off) red[tid] += red[tid + off];
        __syncthreads();
    }
    const float inv = 1.f / red[0];
    if (tid < DBINS)
        dp[(cam*DBINS + tid) * NPIX + p] = e * inv;
}

// ---------------- trilinear grid-sample + cam-sum + mask-normalize ----------------
__global__ __launch_bounds__(256)
void sample_kernel(const float* __restrict__ grid,   // [6][128][128][16][3]
                   const float* __restrict__ dp,     // [6][112][32][88]
                   float* __restrict__ out)          // [262144]
{
    const int v = blockIdx.x * blockDim.x + threadIdx.x;
    if (v >= NVOX) return;

    float agg = 0.f, mask = 0.f;
    #pragma unroll 1
    for (int cam = 0; cam < NCAM; cam++) {
        const float* g = grid + ((size_t)cam * NVOX + v) * 3;
        const float gx = g[0], gy = g[1], gz = g[2];
        const float ix = ((gx + 1.f) * 88.f  - 1.f) * 0.5f;
        const float iy = ((gy + 1.f) * 32.f  - 1.f) * 0.5f;
        const float iz = ((gz + 1.f) * 112.f - 1.f) * 0.5f;
        const float fx0 = floorf(ix), fy0 = floorf(iy), fz0 = floorf(iz);
        const float fx = ix - fx0, fy = iy - fy0, fz = iz - fz0;
        const int x0 = (int)fx0, y0 = (int)fy0, z0 = (int)fz0;
        const float* dc = dp + cam * DBINS * NPIX;
        #pragma unroll
        for (int dz = 0; dz < 2; dz++)
            #pragma unroll
            for (int dy = 0; dy < 2; dy++)
                #pragma unroll
                for (int dx = 0; dx < 2; dx++) {
                    const int xi = x0 + dx, yi = y0 + dy, zi = z0 + dz;
                    const float wv = (dx ? fx : 1.f - fx) * (dy ? fy : 1.f - fy) * (dz ? fz : 1.f - fz);
                    if (xi >= 0 && xi < WW && yi >= 0 && yi < HH && zi >= 0 && zi < DBINS) {
                        agg  += wv * dc[zi * NPIX + yi*WW + xi];
                        mask += wv;
                    }
                }
    }
    out[v] = (mask > 0.f) ? (agg / mask) : agg;
}

// ---------------- launch ----------------
extern "C" void kernel_launch(void* const* d_in, const int* in_sizes, int n_in,
                              void* d_out, int out_size)
{
    const float* img    = (const float*)d_in[0];
    const float* intr   = (const float*)d_in[1];
    const float* grid   = (const float*)d_in[2];
    const float* red_w  = (const float*)d_in[3];
    const float* red_s  = (const float*)d_in[4];
    const float* red_b  = (const float*)d_in[5];
    const float* mlp_w1 = (const float*)d_in[6];
    const float* mlp_b1 = (const float*)d_in[7];
    const float* mlp_w2 = (const float*)d_in[8];
    const float* mlp_b2 = (const float*)d_in[9];
    const float* se_rw  = (const float*)d_in[10];
    const float* se_rb  = (const float*)d_in[11];
    const float* se_ew  = (const float*)d_in[12];
    const float* se_eb  = (const float*)d_in[13];
    const float* bb_w   = (const float*)d_in[14];
    const float* bb_s   = (const float*)d_in[15];
    const float* bb_b   = (const float*)d_in[16];
    const float* dp_w   = (const float*)d_in[17];
    const float* dp_b   = (const float*)d_in[18];

    float *px, *py, *pdp, *pg;
    cudaGetSymbolAddress((void**)&px,  g_x);
    cudaGetSymbolAddress((void**)&py,  g_y);
    cudaGetSymbolAddress((void**)&pdp, g_dp);
    cudaGetSymbolAddress((void**)&pg,  g_gate);

    // 1) SE gate
    gate_kernel<<<NCAM, 256>>>(intr, mlp_w1, mlp_b1, mlp_w2, mlp_b2,
                               se_rw, se_rb, se_ew, se_eb, pg);

    // 2) reduce conv 512->256 (+scale/bias/relu, *gate)
    dim3 cgrid(3, 4, NCAM * 16);
    conv3x3_kernel<CIN_IMG, 0><<<cgrid, 128>>>(img, red_w, red_s, red_b, pg, px);

    // 3) three residual blocks
    const size_t WSTEP = (size_t)MID * MID * 9;
    for (int i = 0; i < 3; i++) {
        conv3x3_kernel<MID, 1><<<cgrid, 128>>>(px, bb_w + (size_t)(2*i)   * WSTEP,
                                               bb_s + (2*i)*MID,   bb_b + (2*i)*MID,
                                               nullptr, py);
        conv3x3_kernel<MID, 2><<<cgrid, 128>>>(py, bb_w + (size_t)(2*i+1) * WSTEP,
                                               bb_s + (2*i+1)*MID, bb_b + (2*i+1)*MID,
                                               px, px);
    }

    // 4) depth head + softmax
    depth_softmax_kernel<<<NCAM * NPIX, 128>>>(px, dp_w, dp_b, pdp);

    // 5) trilinear sample + camera sum + normalize
    sample_kernel<<<(NVOX + 255) / 256, 256>>>(grid, pdp, (float*)d_out);
}